// round 14
// baseline (speedup 1.0000x reference)
#include <cuda_runtime.h>
#include <cstdint>

#define COLS    16384
#define THREADS 512
#define VITER   8                 // uint4 per thread (32 elems)
#define NB      512               // fast-path bins (1536..2047)
#define NB_FULL 2048
#define CAP     2048
#define ZWORDS  2048              // 8 KB zero buffer for TMA bulk stores
#define PIVOT0  0xC0000000u       // key_of(+2.0f), bin-1536 aligned
#define RAWPIV  0x40000000        // (int)u >= RAWPIV  <=>  key_of(u) >= PIVOT0

__device__ __forceinline__ unsigned key_of(unsigned u) {
    return u ^ (unsigned)(((int)u >> 31) | (int)0x80000000);
}
__device__ __forceinline__ float val_of(unsigned kx) {
    return __uint_as_float(kx ^ (unsigned)((~((int)kx >> 31)) | (int)0x80000000));
}

__global__ void __launch_bounds__(THREADS, 4)
topk_threshold_kernel(const float* __restrict__ x,
                      float* __restrict__ out,
                      const int* __restrict__ kptr)
{
    __shared__ unsigned       ckey[CAP];     // 8 KB; fallback reuse: 2048-bin hist
    __shared__ unsigned short cpos[CAP];     // 4 KB
    __shared__ unsigned       hist[NB];      // 2 KB; reused as tie-bin buffer
    __shared__ unsigned       zbuf[ZWORDS];  // 8 KB of zeros (TMA bulk-store source)
    __shared__ unsigned wsum[16];
    __shared__ unsigned sh_cnt, sh_bin, sh_krem, sh_bincnt, sh_cnt2, sh_c, sh_tkey;

    const int tid  = threadIdx.x;
    const int lane = tid & 31;
    const int wid  = tid >> 5;
    const size_t row_off = (size_t)blockIdx.x * COLS;
    const uint4* __restrict__ xin = (const uint4*)(x + row_off);
    float4* __restrict__ oout     = (float4*)(out + row_off);
    float*  __restrict__ oscal    = out + row_off;

    const unsigned k = kptr ? (unsigned)__ldg(kptr) : 64u;

    if (tid < NB) hist[tid] = 0u;
    #pragma unroll
    for (int i = tid; i < ZWORDS; i += THREADS) zbuf[i] = 0u;
    if (tid == 0) { sh_cnt = 0u; sh_cnt2 = 0u; }
    __syncthreads();

    // ---- Kick off the entire zero write stream via TMA bulk stores ----
    if (tid == 0) {
        asm volatile("fence.proxy.async.shared::cta;" ::: "memory");
        unsigned zsrc = (unsigned)__cvta_generic_to_shared(zbuf);
        #pragma unroll
        for (int c = 0; c < 8; c++) {
            asm volatile(
                "cp.async.bulk.global.shared::cta.bulk_group [%0], [%1], %2;"
                :: "l"(oscal + c * ZWORDS), "r"(zsrc), "r"((unsigned)(ZWORDS * 4))
                : "memory");
        }
        asm volatile("cp.async.bulk.commit_group;" ::: "memory");
    }

    // ---- Fused pass: paired loads (MLP=2), gather candidates + fused histogram ----
    #pragma unroll
    for (int b = 0; b < VITER / 2; b++) {
        const int i0 = tid + (2 * b + 0) * THREADS;
        const int i1 = tid + (2 * b + 1) * THREADS;
        uint4 v0 = __ldcs(&xin[i0]);      // two independent loads in flight
        uint4 v1 = __ldcs(&xin[i1]);
        #pragma unroll
        for (int j = 0; j < 4; j++) {
            unsigned u = ((const unsigned*)&v0)[j];
            if ((int)u >= RAWPIV) {
                unsigned ky = key_of(u);
                unsigned p = atomicAdd(&sh_cnt, 1u);
                if (p < CAP) { ckey[p] = ky; cpos[p] = (unsigned short)(i0 * 4 + j); }
                atomicAdd(&hist[(ky >> 21) - 1536u], 1u);
            }
        }
        #pragma unroll
        for (int j = 0; j < 4; j++) {
            unsigned u = ((const unsigned*)&v1)[j];
            if ((int)u >= RAWPIV) {
                unsigned ky = key_of(u);
                unsigned p = atomicAdd(&sh_cnt, 1u);
                if (p < CAP) { ckey[p] = ky; cpos[p] = (unsigned short)(i1 * 4 + j); }
                atomicAdd(&hist[(ky >> 21) - 1536u], 1u);
            }
        }
    }
    __syncthreads();

    const unsigned ncand = sh_cnt;
    const bool fast = (ncand >= k) && (ncand <= CAP);

    if (fast) {
        // ---- Bin select: suffix-sum scan over 512 bins, 1 bin/thread ----
        unsigned gs = hist[tid];
        unsigned s = gs;
        #pragma unroll
        for (int off = 1; off < 32; off <<= 1) {
            unsigned v = __shfl_down_sync(0xFFFFFFFFu, s, off);
            if (lane + off < 32) s += v;
        }
        if (lane == 0) wsum[wid] = s;
        __syncthreads();
        unsigned woff = 0;
        #pragma unroll
        for (int w = 0; w < 16; w++) woff += (w > wid) ? wsum[w] : 0u;
        unsigned ssum = s + woff;
        if (ssum >= k && (ssum - gs) < k) {
            sh_bin    = (unsigned)tid + 1536u;
            sh_krem   = k - (ssum - gs);
            sh_bincnt = gs;
        }
        __syncthreads();
        const unsigned binp   = sh_bin;
        const unsigned krem1  = sh_krem;
        const unsigned bincnt = sh_bincnt;

        if (bincnt <= NB) {
            // ---- Compact tie-bin keys into hist (dead now) ----
            unsigned* cand2 = hist;
            for (int i = tid; i < (int)ncand; i += THREADS) {
                unsigned ky = ckey[i];
                if ((ky >> 21) == binp) cand2[atomicAdd(&sh_cnt2, 1u)] = ky;
            }
            __syncthreads();

            // ---- One-shot parallel rank select (thread i ranks key i) ----
            const int n = (int)sh_cnt2;
            if (tid < n) {
                unsigned ki = cand2[tid];
                unsigned gt = 0, eq = 0;
                for (int j = 0; j < n; j++) {        // broadcast reads
                    unsigned kj = cand2[j];
                    gt += (kj > ki);
                    eq += (kj == ki);
                }
                if (gt < krem1 && gt + eq >= krem1) sh_tkey = ki;
            }
            __syncthreads();
        } else {
            // huge tie bin (candidates all in smem): block bitwise select
            unsigned krem = krem1, cur = 0u;
            for (int bit = 20; bit >= 0; bit--) {
                if (tid == 0) sh_c = 0u;
                __syncthreads();
                unsigned want  = (cur << 1) | 1u;
                unsigned fullw = (binp << (21 - bit)) | want;
                unsigned local = 0;
                for (int i = tid; i < (int)ncand; i += THREADS)
                    local += ((ckey[i] >> bit) == fullw);
                local = __reduce_add_sync(0xFFFFFFFFu, local);
                if (lane == 0) atomicAdd(&sh_c, local);
                __syncthreads();
                unsigned cnt = sh_c;
                if (cnt >= krem) cur = want;
                else { cur = want - 1u; krem -= cnt; }
                __syncthreads();
            }
            if (tid == 0) sh_tkey = (binp << 21) | cur;
            __syncthreads();
        }

        // ---- Wait for zero stream, then scatter fix-up ----
        if (tid == 0) asm volatile("cp.async.bulk.wait_group 0;" ::: "memory");
        __syncthreads();
        const unsigned tkey = sh_tkey;
        for (int i = tid; i < (int)ncand; i += THREADS) {
            unsigned ky = ckey[i];
            if (ky >= tkey) oscal[cpos[i]] = val_of(ky);
        }
    } else {
        // ================= FALLBACK (exact, any input; never for Gaussian) ========
        unsigned* hist2 = ckey;   // 2048-entry histogram in candidate buffer
        for (int b = tid; b < NB_FULL; b += THREADS) hist2[b] = 0u;
        __syncthreads();
        #pragma unroll
        for (int i = 0; i < VITER; i++) {
            uint4 v = xin[tid + i * THREADS];
            atomicAdd(&hist2[key_of(v.x) >> 21], 1u);
            atomicAdd(&hist2[key_of(v.y) >> 21], 1u);
            atomicAdd(&hist2[key_of(v.z) >> 21], 1u);
            atomicAdd(&hist2[key_of(v.w) >> 21], 1u);
        }
        __syncthreads();

        unsigned gs = hist2[tid*4] + hist2[tid*4+1] + hist2[tid*4+2] + hist2[tid*4+3];
        unsigned s = gs;
        #pragma unroll
        for (int off = 1; off < 32; off <<= 1) {
            unsigned v = __shfl_down_sync(0xFFFFFFFFu, s, off);
            if (lane + off < 32) s += v;
        }
        if (lane == 0) wsum[wid] = s;
        __syncthreads();
        unsigned woff = 0;
        #pragma unroll
        for (int w = 0; w < 16; w++) woff += (w > wid) ? wsum[w] : 0u;
        unsigned ssum = s + woff;
        if (ssum >= k && (ssum - gs) < k) {
            unsigned above = ssum - gs;
            int b = 0;
            #pragma unroll
            for (int bb = 3; bb >= 0; bb--) {
                unsigned c = hist2[tid * 4 + bb];
                if (above + c >= k) { b = bb; break; }
                above += c;
            }
            sh_bin    = (unsigned)(tid * 4 + b);
            sh_krem   = k - above;
            sh_bincnt = hist2[tid * 4 + b];
        }
        __syncthreads();
        const unsigned binp   = sh_bin;
        const unsigned krem1  = sh_krem;
        const unsigned bincnt = sh_bincnt;

        if (bincnt <= NB) {
            unsigned* cand2 = hist;
            #pragma unroll
            for (int i = 0; i < VITER; i++) {
                uint4 v = xin[tid + i * THREADS];
                #pragma unroll
                for (int j = 0; j < 4; j++) {
                    unsigned ky = key_of(((const unsigned*)&v)[j]);
                    if ((ky >> 21) == binp) cand2[atomicAdd(&sh_cnt2, 1u)] = ky;
                }
            }
            __syncthreads();
            const int n = (int)sh_cnt2;
            if (tid < n) {
                unsigned ki = cand2[tid];
                unsigned gt = 0, eq = 0;
                for (int j = 0; j < n; j++) {
                    unsigned kj = cand2[j];
                    gt += (kj > ki);
                    eq += (kj == ki);
                }
                if (gt < krem1 && gt + eq >= krem1) sh_tkey = ki;
            }
            __syncthreads();
        } else {
            unsigned krem = krem1, cur = 0u;
            for (int bit = 20; bit >= 0; bit--) {
                if (tid == 0) sh_c = 0u;
                __syncthreads();
                unsigned want  = (cur << 1) | 1u;
                unsigned fullw = (binp << (21 - bit)) | want;
                unsigned local = 0;
                #pragma unroll
                for (int i = 0; i < VITER; i++) {
                    uint4 v = xin[tid + i * THREADS];
                    local += ((key_of(v.x) >> bit) == fullw);
                    local += ((key_of(v.y) >> bit) == fullw);
                    local += ((key_of(v.z) >> bit) == fullw);
                    local += ((key_of(v.w) >> bit) == fullw);
                }
                local = __reduce_add_sync(0xFFFFFFFFu, local);
                if (lane == 0) atomicAdd(&sh_c, local);
                __syncthreads();
                unsigned cnt = sh_c;
                if (cnt >= krem) cur = want;
                else { cur = want - 1u; krem -= cnt; }
                __syncthreads();
            }
            if (tid == 0) sh_tkey = (binp << 21) | cur;
            __syncthreads();
        }

        // wait for zero stream, then full rewrite with exact float threshold
        if (tid == 0) asm volatile("cp.async.bulk.wait_group 0;" ::: "memory");
        __syncthreads();
        const float t = val_of(sh_tkey);
        #pragma unroll
        for (int i = 0; i < VITER; i++) {
            float4 v = ((const float4*)xin)[tid + i * THREADS];
            float4 o;
            o.x = (v.x >= t) ? v.x : 0.0f;
            o.y = (v.y >= t) ? v.y : 0.0f;
            o.z = (v.z >= t) ? v.z : 0.0f;
            o.w = (v.w >= t) ? v.w : 0.0f;
            oout[tid + i * THREADS] = o;
        }
    }
}

extern "C" void kernel_launch(void* const* d_in, const int* in_sizes, int n_in,
                              void* d_out, int out_size) {
    const float* x  = (const float*)d_in[0];
    const int* kptr = (n_in > 1) ? (const int*)d_in[1] : nullptr;
    const int rows  = in_sizes[0] / COLS;
    topk_threshold_kernel<<<rows, THREADS>>>(x, (float*)d_out, kptr);
}

// round 15
// speedup vs baseline: 1.0103x; 1.0103x over previous
#include <cuda_runtime.h>
#include <cstdint>

#define COLS    16384
#define THREADS 512
#define VITER   8                 // (fallback paths) uint4 per thread
#define V8ITER  4                 // 256-bit loads per thread (32 elems)
#define NB      512               // fast-path bins (1536..2047)
#define NB_FULL 2048
#define CAP     2048
#define ZWORDS  2048              // 8 KB zero buffer for TMA bulk stores
#define PIVOT0  0xC0000000u       // key_of(+2.0f), bin-1536 aligned
#define RAWPIV  0x40000000        // (int)u >= RAWPIV  <=>  key_of(u) >= PIVOT0

__device__ __forceinline__ unsigned key_of(unsigned u) {
    return u ^ (unsigned)(((int)u >> 31) | (int)0x80000000);
}
__device__ __forceinline__ float val_of(unsigned kx) {
    return __uint_as_float(kx ^ (unsigned)((~((int)kx >> 31)) | (int)0x80000000));
}

__global__ void __launch_bounds__(THREADS, 4)
topk_threshold_kernel(const float* __restrict__ x,
                      float* __restrict__ out,
                      const int* __restrict__ kptr)
{
    __shared__ unsigned       ckey[CAP];     // 8 KB; fallback reuse: 2048-bin hist
    __shared__ unsigned short cpos[CAP];     // 4 KB
    __shared__ unsigned       hist[NB];      // 2 KB; reused as tie-bin buffer
    __shared__ unsigned       zbuf[ZWORDS];  // 8 KB of zeros (TMA bulk-store source)
    __shared__ unsigned wsum[16];
    __shared__ unsigned sh_cnt, sh_bin, sh_krem, sh_bincnt, sh_cnt2, sh_c, sh_tkey;

    const int tid  = threadIdx.x;
    const int lane = tid & 31;
    const int wid  = tid >> 5;
    const size_t row_off = (size_t)blockIdx.x * COLS;
    const unsigned* __restrict__ xu = (const unsigned*)(x + row_off);
    const uint4* __restrict__ xin   = (const uint4*)(x + row_off);
    float4* __restrict__ oout       = (float4*)(out + row_off);
    float*  __restrict__ oscal      = out + row_off;

    const unsigned k = kptr ? (unsigned)__ldg(kptr) : 64u;

    if (tid < NB) hist[tid] = 0u;
    #pragma unroll
    for (int i = tid; i < ZWORDS; i += THREADS) zbuf[i] = 0u;
    if (tid == 0) { sh_cnt = 0u; sh_cnt2 = 0u; }
    __syncthreads();

    // ---- Kick off the entire zero write stream via TMA bulk stores ----
    if (tid == 0) {
        asm volatile("fence.proxy.async.shared::cta;" ::: "memory");
        unsigned zsrc = (unsigned)__cvta_generic_to_shared(zbuf);
        #pragma unroll
        for (int c = 0; c < 8; c++) {
            asm volatile(
                "cp.async.bulk.global.shared::cta.bulk_group [%0], [%1], %2;"
                :: "l"(oscal + c * ZWORDS), "r"(zsrc), "r"((unsigned)(ZWORDS * 4))
                : "memory");
        }
        asm volatile("cp.async.bulk.commit_group;" ::: "memory");
    }

    // ---- Fused pass: 256-bit loads, gather candidates + fused histogram ----
    #pragma unroll
    for (int i = 0; i < V8ITER; i++) {
        const int vidx = tid + i * THREADS;          // uint8-vector index
        unsigned a0, a1, a2, a3, a4, a5, a6, a7;
        asm volatile(
            "ld.global.cs.v8.u32 {%0,%1,%2,%3,%4,%5,%6,%7}, [%8];"
            : "=r"(a0), "=r"(a1), "=r"(a2), "=r"(a3),
              "=r"(a4), "=r"(a5), "=r"(a6), "=r"(a7)
            : "l"(xu + (size_t)vidx * 8));
        unsigned va[8] = {a0, a1, a2, a3, a4, a5, a6, a7};
        #pragma unroll
        for (int j = 0; j < 8; j++) {
            unsigned u = va[j];
            if ((int)u >= RAWPIV) {                  // <=> key_of(u) >= PIVOT0
                unsigned ky = key_of(u);
                unsigned p = atomicAdd(&sh_cnt, 1u);
                if (p < CAP) { ckey[p] = ky; cpos[p] = (unsigned short)(vidx * 8 + j); }
                atomicAdd(&hist[(ky >> 21) - 1536u], 1u);   // fused histogram
            }
        }
    }
    __syncthreads();

    const unsigned ncand = sh_cnt;
    const bool fast = (ncand >= k) && (ncand <= CAP);

    if (fast) {
        // ---- Bin select: suffix-sum scan over 512 bins, 1 bin/thread ----
        unsigned gs = hist[tid];
        unsigned s = gs;
        #pragma unroll
        for (int off = 1; off < 32; off <<= 1) {
            unsigned v = __shfl_down_sync(0xFFFFFFFFu, s, off);
            if (lane + off < 32) s += v;
        }
        if (lane == 0) wsum[wid] = s;
        __syncthreads();
        unsigned woff = 0;
        #pragma unroll
        for (int w = 0; w < 16; w++) woff += (w > wid) ? wsum[w] : 0u;
        unsigned ssum = s + woff;
        if (ssum >= k && (ssum - gs) < k) {
            sh_bin    = (unsigned)tid + 1536u;
            sh_krem   = k - (ssum - gs);
            sh_bincnt = gs;
        }
        __syncthreads();
        const unsigned binp   = sh_bin;
        const unsigned krem1  = sh_krem;
        const unsigned bincnt = sh_bincnt;

        if (bincnt <= NB) {
            // ---- Compact tie-bin keys into hist (dead now) ----
            unsigned* cand2 = hist;
            for (int i = tid; i < (int)ncand; i += THREADS) {
                unsigned ky = ckey[i];
                if ((ky >> 21) == binp) cand2[atomicAdd(&sh_cnt2, 1u)] = ky;
            }
            __syncthreads();

            // ---- One-shot parallel rank select (thread i ranks key i) ----
            const int n = (int)sh_cnt2;
            if (tid < n) {
                unsigned ki = cand2[tid];
                unsigned gt = 0, eq = 0;
                for (int j = 0; j < n; j++) {        // broadcast reads
                    unsigned kj = cand2[j];
                    gt += (kj > ki);
                    eq += (kj == ki);
                }
                if (gt < krem1 && gt + eq >= krem1) sh_tkey = ki;
            }
            __syncthreads();
        } else {
            // huge tie bin (candidates all in smem): block bitwise select
            unsigned krem = krem1, cur = 0u;
            for (int bit = 20; bit >= 0; bit--) {
                if (tid == 0) sh_c = 0u;
                __syncthreads();
                unsigned want  = (cur << 1) | 1u;
                unsigned fullw = (binp << (21 - bit)) | want;
                unsigned local = 0;
                for (int i = tid; i < (int)ncand; i += THREADS)
                    local += ((ckey[i] >> bit) == fullw);
                local = __reduce_add_sync(0xFFFFFFFFu, local);
                if (lane == 0) atomicAdd(&sh_c, local);
                __syncthreads();
                unsigned cnt = sh_c;
                if (cnt >= krem) cur = want;
                else { cur = want - 1u; krem -= cnt; }
                __syncthreads();
            }
            if (tid == 0) sh_tkey = (binp << 21) | cur;
            __syncthreads();
        }

        // ---- Wait for zero stream, then scatter fix-up ----
        if (tid == 0) asm volatile("cp.async.bulk.wait_group 0;" ::: "memory");
        __syncthreads();
        const unsigned tkey = sh_tkey;
        for (int i = tid; i < (int)ncand; i += THREADS) {
            unsigned ky = ckey[i];
            if (ky >= tkey) oscal[cpos[i]] = val_of(ky);
        }
    } else {
        // ================= FALLBACK (exact, any input; never for Gaussian) ========
        unsigned* hist2 = ckey;   // 2048-entry histogram in candidate buffer
        for (int b = tid; b < NB_FULL; b += THREADS) hist2[b] = 0u;
        __syncthreads();
        #pragma unroll
        for (int i = 0; i < VITER; i++) {
            uint4 v = xin[tid + i * THREADS];
            atomicAdd(&hist2[key_of(v.x) >> 21], 1u);
            atomicAdd(&hist2[key_of(v.y) >> 21], 1u);
            atomicAdd(&hist2[key_of(v.z) >> 21], 1u);
            atomicAdd(&hist2[key_of(v.w) >> 21], 1u);
        }
        __syncthreads();

        unsigned gs = hist2[tid*4] + hist2[tid*4+1] + hist2[tid*4+2] + hist2[tid*4+3];
        unsigned s = gs;
        #pragma unroll
        for (int off = 1; off < 32; off <<= 1) {
            unsigned v = __shfl_down_sync(0xFFFFFFFFu, s, off);
            if (lane + off < 32) s += v;
        }
        if (lane == 0) wsum[wid] = s;
        __syncthreads();
        unsigned woff = 0;
        #pragma unroll
        for (int w = 0; w < 16; w++) woff += (w > wid) ? wsum[w] : 0u;
        unsigned ssum = s + woff;
        if (ssum >= k && (ssum - gs) < k) {
            unsigned above = ssum - gs;
            int b = 0;
            #pragma unroll
            for (int bb = 3; bb >= 0; bb--) {
                unsigned c = hist2[tid * 4 + bb];
                if (above + c >= k) { b = bb; break; }
                above += c;
            }
            sh_bin    = (unsigned)(tid * 4 + b);
            sh_krem   = k - above;
            sh_bincnt = hist2[tid * 4 + b];
        }
        __syncthreads();
        const unsigned binp   = sh_bin;
        const unsigned krem1  = sh_krem;
        const unsigned bincnt = sh_bincnt;

        if (bincnt <= NB) {
            unsigned* cand2 = hist;
            #pragma unroll
            for (int i = 0; i < VITER; i++) {
                uint4 v = xin[tid + i * THREADS];
                #pragma unroll
                for (int j = 0; j < 4; j++) {
                    unsigned ky = key_of(((const unsigned*)&v)[j]);
                    if ((ky >> 21) == binp) cand2[atomicAdd(&sh_cnt2, 1u)] = ky;
                }
            }
            __syncthreads();
            const int n = (int)sh_cnt2;
            if (tid < n) {
                unsigned ki = cand2[tid];
                unsigned gt = 0, eq = 0;
                for (int j = 0; j < n; j++) {
                    unsigned kj = cand2[j];
                    gt += (kj > ki);
                    eq += (kj == ki);
                }
                if (gt < krem1 && gt + eq >= krem1) sh_tkey = ki;
            }
            __syncthreads();
        } else {
            unsigned krem = krem1, cur = 0u;
            for (int bit = 20; bit >= 0; bit--) {
                if (tid == 0) sh_c = 0u;
                __syncthreads();
                unsigned want  = (cur << 1) | 1u;
                unsigned fullw = (binp << (21 - bit)) | want;
                unsigned local = 0;
                #pragma unroll
                for (int i = 0; i < VITER; i++) {
                    uint4 v = xin[tid + i * THREADS];
                    local += ((key_of(v.x) >> bit) == fullw);
                    local += ((key_of(v.y) >> bit) == fullw);
                    local += ((key_of(v.z) >> bit) == fullw);
                    local += ((key_of(v.w) >> bit) == fullw);
                }
                local = __reduce_add_sync(0xFFFFFFFFu, local);
                if (lane == 0) atomicAdd(&sh_c, local);
                __syncthreads();
                unsigned cnt = sh_c;
                if (cnt >= krem) cur = want;
                else { cur = want - 1u; krem -= cnt; }
                __syncthreads();
            }
            if (tid == 0) sh_tkey = (binp << 21) | cur;
            __syncthreads();
        }

        // wait for zero stream, then full rewrite with exact float threshold
        if (tid == 0) asm volatile("cp.async.bulk.wait_group 0;" ::: "memory");
        __syncthreads();
        const float t = val_of(sh_tkey);
        #pragma unroll
        for (int i = 0; i < VITER; i++) {
            float4 v = ((const float4*)xin)[tid + i * THREADS];
            float4 o;
            o.x = (v.x >= t) ? v.x : 0.0f;
            o.y = (v.y >= t) ? v.y : 0.0f;
            o.z = (v.z >= t) ? v.z : 0.0f;
            o.w = (v.w >= t) ? v.w : 0.0f;
            oout[tid + i * THREADS] = o;
        }
    }
}

extern "C" void kernel_launch(void* const* d_in, const int* in_sizes, int n_in,
                              void* d_out, int out_size) {
    const float* x  = (const float*)d_in[0];
    const int* kptr = (n_in > 1) ? (const int*)d_in[1] : nullptr;
    const int rows  = in_sizes[0] / COLS;
    topk_threshold_kernel<<<rows, THREADS>>>(x, (float*)d_out, kptr);
}